// round 15
// baseline (speedup 1.0000x reference)
#include <cuda_runtime.h>
#include <cuda_bf16.h>
#include <cuda_fp8.h>
#include <math.h>
#include <stdint.h>

#define B_ROWS 16384
#define NCLS   1000
#define CF     1280
#define NPAD   1024

#define NT_COV 55                 // 128x128 lower-tri tiles (split-K 2)
#define NT_ORT 36                 // 128x128 lower-tri tiles
#define SPLITC 2
#define KSPLIT (B_ROWS / SPLITC)  // 8192
#define NSTEP_COV (KSPLIT / 128)  // 64
#define NSTEP_ORT (CF / 128)      // 10

#define STAGES      4
#define STAGE_BYTES 32768
#define SMEM_MMA    (STAGES * STAGE_BYTES)

#define WSCALE 64.0f
#define WSCALE2_INV (1.0f / 4096.0f)

#define NB_W   384
#define NB_N   128
#define NB_F   (B_ROWS / 32)      // 512
#define NB_CR  512

// ---------------- device scratch ----------------
__device__ float  g_musum[CF];
__device__ float  g_p1[NB_W], g_p2[NB_W];
__device__ float  g_pn[NB_N];
__device__ float  g_klp2[NB_F];
__device__ double g_cvp[NB_CR];
__device__ double g_otp[NT_ORT];
__device__ __align__(256) uint8_t g_Ft8[CF][B_ROWS];
__device__ __align__(256) uint8_t g_Wb8[NPAD][CF];
__device__ float g_covp[SPLITC][CF * CF];

// ---------------- helpers ----------------
__device__ __forceinline__ float warpSum(float v) {
    #pragma unroll
    for (int o = 16; o; o >>= 1) v += __shfl_xor_sync(0xffffffffu, v, o);
    return v;
}
__device__ __forceinline__ uint32_t smem_u32(const void* p) {
    uint32_t a;
    asm("{ .reg .u64 t; cvta.to.shared.u64 t, %1; cvt.u32.u64 %0, t; }" : "=r"(a) : "l"(p));
    return a;
}
__device__ __forceinline__ uint32_t sw128(uint32_t off) {
    return off ^ ((off >> 3) & 0x70);
}
__device__ __forceinline__ void cp16(uint32_t saddr, const void* g) {
    asm volatile("cp.async.cg.shared.global [%0], [%1], 16;" :: "r"(saddr), "l"(g) : "memory");
}
__device__ __forceinline__ void ldsm4(uint32_t* r, uint32_t addr) {
    asm volatile("ldmatrix.sync.aligned.m8n8.x4.shared.b16 {%0,%1,%2,%3}, [%4];"
                 : "=r"(r[0]), "=r"(r[1]), "=r"(r[2]), "=r"(r[3]) : "r"(addr));
}
__device__ __forceinline__ void mma_fp8(float* d, const uint32_t* a, uint32_t b0, uint32_t b1) {
    asm volatile(
        "mma.sync.aligned.m16n8k32.row.col.f32.e4m3.e4m3.f32 "
        "{%0,%1,%2,%3}, {%4,%5,%6,%7}, {%8,%9}, {%0,%1,%2,%3};"
        : "+f"(d[0]), "+f"(d[1]), "+f"(d[2]), "+f"(d[3])
        : "r"(a[0]), "r"(a[1]), "r"(a[2]), "r"(a[3]), "r"(b0), "r"(b1));
}
__device__ __forceinline__ uint32_t pack4_e4m3(float a0, float a1, float a2, float a3) {
    uint16_t lo, hi;
    asm("cvt.rn.satfinite.e4m3x2.f32 %0, %1, %2;" : "=h"(lo) : "f"(a1), "f"(a0));
    asm("cvt.rn.satfinite.e4m3x2.f32 %0, %1, %2;" : "=h"(hi) : "f"(a3), "f"(a2));
    return (uint32_t)lo | ((uint32_t)hi << 16);
}

// ---------------- k_pre: wconv + nll + musum-zero ----------------
__global__ __launch_bounds__(256) void k_pre(const float* __restrict__ W,
                                             const float* __restrict__ out,
                                             const void* __restrict__ tgtraw) {
    int tid = threadIdx.x;
    if (blockIdx.x < NB_W) {
        __shared__ float s1[8], s2[8];
        int gid = blockIdx.x * 256 + tid;
        int stride = NB_W * 256;
        float a = 0.f, q = 0.f;
        const int nf4 = NCLS * CF / 4;
        for (int i = gid; i < nf4; i += stride) {
            float4 w = *((const float4*)W + i);
            a += (fabsf(w.x) + fabsf(w.y)) + (fabsf(w.z) + fabsf(w.w));
            q = fmaf(w.x, w.x, fmaf(w.y, w.y, fmaf(w.z, w.z, fmaf(w.w, w.w, q))));
            *(uint32_t*)&g_Wb8[0][i * 4] = pack4_e4m3(w.x * WSCALE, w.y * WSCALE,
                                                      w.z * WSCALE, w.w * WSCALE);
        }
        const int padw = (NPAD - NCLS) * CF / 4;
        for (int i = gid; i < padw; i += stride)
            *((uint32_t*)&g_Wb8[NCLS][0] + i) = 0u;
        a = warpSum(a); q = warpSum(q);
        if ((tid & 31) == 0) { s1[tid >> 5] = a; s2[tid >> 5] = q; }
        __syncthreads();
        if (tid == 0) {
            float aa = 0.f, qq = 0.f;
            #pragma unroll
            for (int i = 0; i < 8; i++) { aa += s1[i]; qq += s2[i]; }
            g_p1[blockIdx.x] = aa;
            g_p2[blockIdx.x] = qq;
        }
    } else {
        __shared__ float swk[8];
        __shared__ int s_is64;
        const int* t32 = (const int*)tgtraw;
        int b0 = blockIdx.x - NB_W;
        int zi = b0 * 256 + tid;
        if (zi < CF) g_musum[zi] = 0.f;
        if (tid == 0) {
            int all0 = 1;
            #pragma unroll
            for (int k = 0; k < 32; k++) all0 &= (t32[2 * k + 1] == 0);
            s_is64 = all0;
        }
        __syncthreads();
        int is64 = s_is64;
        int gid = b0 * 256 + tid;
        int stride = NB_N * 256;
        float v = 0.f;
        for (int b = gid; b < B_ROWS; b += stride) {
            int idx = is64 ? (int)((const long long*)tgtraw)[b] : t32[b];
            idx = min(max(idx, 0), NCLS - 1);
            v += out[(size_t)b * NCLS + idx];
        }
        v = warpSum(v);
        if ((tid & 31) == 0) swk[tid >> 5] = v;
        __syncthreads();
        if (tid == 0) {
            float aa = 0.f;
            #pragma unroll
            for (int i = 0; i < 8; i++) aa += swk[i];
            g_pn[b0] = aa;
        }
    }
}

// ---------------- fused F pass: quad chunks (MLP=4, 10 barriers) ----------
__global__ __launch_bounds__(256) void k_fpass(const float* __restrict__ F) {
    __shared__ float ts[2][4][32][33];
    __shared__ float srow[32];
    int r0 = blockIdx.x * 32;
    int t = threadIdx.x;
    int lane = t & 31;
    int r  = t >> 3;
    int u  = t & 7;
    int c4 = u * 4;
    int cc = t >> 3;
    int rs = u * 4;

    const float4* frow = (const float4*)(F + (size_t)(r0 + r) * CF);
    float sx = 0.f, se = 0.f, sex = 0.f;

    for (int p = 0; p < 10; p++) {
        int pb = p & 1;
        float4 v[4];
        #pragma unroll
        for (int h = 0; h < 4; h++) v[h] = frow[(4 * p + h) * 8 + u];

        #pragma unroll
        for (int h = 0; h < 4; h++) {
            float e0 = __expf(v[h].x), e1 = __expf(v[h].y);
            float e2 = __expf(v[h].z), e3 = __expf(v[h].w);
            sx += (v[h].x + v[h].y) + (v[h].z + v[h].w);
            se += (e0 + e1) + (e2 + e3);
            sex = fmaf(e0, v[h].x, fmaf(e1, v[h].y, fmaf(e2, v[h].z, fmaf(e3, v[h].w, sex))));
            ts[pb][h][r][c4 + 0] = v[h].x;
            ts[pb][h][r][c4 + 1] = v[h].y;
            ts[pb][h][r][c4 + 2] = v[h].z;
            ts[pb][h][r][c4 + 3] = v[h].w;
        }
        __syncthreads();
        #pragma unroll
        for (int h = 0; h < 4; h++) {
            int ch = 4 * p + h;
            float a0 = ts[pb][h][rs + 0][cc];
            float a1 = ts[pb][h][rs + 1][cc];
            float a2 = ts[pb][h][rs + 2][cc];
            float a3 = ts[pb][h][rs + 3][cc];
            float cs = (a0 + a1) + (a2 + a3);
            cs += __shfl_down_sync(0xffffffffu, cs, 4);
            cs += __shfl_down_sync(0xffffffffu, cs, 2);
            cs += __shfl_down_sync(0xffffffffu, cs, 1);
            if ((lane & 7) == 0) atomicAdd(&g_musum[ch * 32 + cc], cs);
            *(uint32_t*)&g_Ft8[ch * 32 + cc][r0 + rs] = pack4_e4m3(a0, a1, a2, a3);
        }
    }

    sx  += __shfl_down_sync(0xffffffffu, sx, 4);
    sx  += __shfl_down_sync(0xffffffffu, sx, 2);
    sx  += __shfl_down_sync(0xffffffffu, sx, 1);
    se  += __shfl_down_sync(0xffffffffu, se, 4);
    se  += __shfl_down_sync(0xffffffffu, se, 2);
    se  += __shfl_down_sync(0xffffffffu, se, 1);
    sex += __shfl_down_sync(0xffffffffu, sex, 4);
    sex += __shfl_down_sync(0xffffffffu, sex, 2);
    sex += __shfl_down_sync(0xffffffffu, sex, 1);
    if ((lane & 7) == 0) srow[r] = (float)CF * (sex / se) - sx;
    __syncthreads();
    if (t < 32) {
        float rv = srow[t];
        rv = warpSum(rv);
        if (t == 0) g_klp2[blockIdx.x] = rv;
    }
}

// ---------------- fp8 MMA: 256 threads, 8 warps, 64x32 warp tiles ---------
__device__ __forceinline__ void issue_loads(uint32_t tbase, const uint8_t* gA,
                                            const uint8_t* gB, int ld, int tid) {
    #pragma unroll
    for (int i = 0; i < 4; i++) {
        int q = tid + i * 256;            // 0..1023
        int r = q >> 3, u = q & 7;
        uint32_t so = sw128((uint32_t)(r * 128 + u * 16));
        cp16(tbase + so, gA + (size_t)r * ld + u * 16);
        cp16(tbase + 16384 + so, gB + (size_t)r * ld + u * 16);
    }
}

__device__ __forceinline__ void mma_step(uint32_t stbase, const uint32_t* pre_a,
                                         const uint32_t* pre_b, float (*acc)[4]) {
    #pragma unroll
    for (int ks = 0; ks < 4; ks++) {
        uint32_t kx = (uint32_t)(ks << 5);
        uint32_t bfr[2][4];
        #pragma unroll
        for (int p = 0; p < 2; p++)
            ldsm4(bfr[p], stbase + (pre_b[p] ^ kx));
        #pragma unroll
        for (int mt = 0; mt < 4; mt++) {
            uint32_t afr[4];
            ldsm4(afr, stbase + (pre_a[mt] ^ kx));
            #pragma unroll
            for (int nt = 0; nt < 4; nt++)
                mma_fp8(acc[mt * 4 + nt], afr,
                        bfr[nt >> 1][(nt & 1) * 2], bfr[nt >> 1][(nt & 1) * 2 + 1]);
        }
    }
}

__global__ __launch_bounds__(256, 1) void k_mma3() {
    extern __shared__ char dsm[];
    uint32_t sbase = smem_u32(dsm);
    int tid = threadIdx.x, wid = tid >> 5, lane = tid & 31;
    int bid = blockIdx.x;

    bool is_cov = bid < SPLITC * NT_COV;
    int split = is_cov ? (bid >= NT_COV ? 1 : 0) : 0;
    int t = is_cov ? (bid - split * NT_COV) : (bid - SPLITC * NT_COV);
    int ti = 0;
    while ((ti + 1) * (ti + 2) / 2 <= t) ++ti;
    int tj = t - ti * (ti + 1) / 2;
    int i0 = ti * 128, j0 = tj * 128;

    const uint8_t* src = is_cov ? &g_Ft8[0][0] : &g_Wb8[0][0];
    const int ld = is_cov ? B_ROWS : CF;
    const size_t koff = is_cov ? (size_t)split * KSPLIT : 0;

    const uint8_t* gA0 = src + (size_t)i0 * ld + koff;
    const uint8_t* gB0 = src + (size_t)j0 * ld + koff;

    int wm = wid >> 2, wn = wid & 3;   // warp tile 64(m) x 32(n)

    float acc[16][4];
    #pragma unroll
    for (int i = 0; i < 16; i++)
        #pragma unroll
        for (int j = 0; j < 4; j++) acc[i][j] = 0.f;

    uint32_t pre_a[4], pre_b[2];
    {
        uint32_t arow = (uint32_t)(wm * 64 + (lane & 15));
        uint32_t ahi  = (uint32_t)((lane >> 4) * 16);
        #pragma unroll
        for (int mt = 0; mt < 4; mt++) {
            uint32_t rr = arow + mt * 16;
            pre_a[mt] = rr * 128 + (ahi ^ ((rr * 16) & 0x70));
        }
        uint32_t brow = (uint32_t)(wn * 32 + (((lane >> 4) & 1) << 3) + (lane & 7));
        uint32_t bhi  = (uint32_t)(((lane >> 3) & 1) * 16);
        #pragma unroll
        for (int p = 0; p < 2; p++) {
            uint32_t rr = brow + p * 16;
            pre_b[p] = 16384u + rr * 128 + (bhi ^ ((rr * 16) & 0x70));
        }
    }

    if (is_cov) {
        // prologue: steps 0,1,2 -> stages 0,1,2
        #pragma unroll
        for (int s = 0; s < 3; s++) {
            issue_loads(sbase + (uint32_t)s * STAGE_BYTES,
                        gA0 + s * 128, gB0 + s * 128, ld, tid);
            asm volatile("cp.async.commit_group;" ::: "memory");
        }
        const uint8_t* gAl = gA0 + 3 * 128;
        const uint8_t* gBl = gB0 + 3 * 128;

        // main: unrolled x4, compile-time stage indices; ms = msb+s
        #pragma unroll 1
        for (int msb = 0; msb < NSTEP_COV - 4; msb += 4) {
            #pragma unroll
            for (int s = 0; s < 4; s++) {
                asm volatile("cp.async.wait_group 2;" ::: "memory");
                __syncthreads();
                issue_loads(sbase + (uint32_t)(((s + 3) & 3)) * STAGE_BYTES,
                            gAl, gBl, ld, tid);
                asm volatile("cp.async.commit_group;" ::: "memory");
                gAl += 128; gBl += 128;
                mma_step(sbase + (uint32_t)s * STAGE_BYTES, pre_a, pre_b, acc);
            }
        }
        // tail: ms = 60..63
        {
            asm volatile("cp.async.wait_group 2;" ::: "memory");  // ms=60
            __syncthreads();
            issue_loads(sbase + 3u * STAGE_BYTES, gAl, gBl, ld, tid);  // step 63
            asm volatile("cp.async.commit_group;" ::: "memory");
            mma_step(sbase + 0u * STAGE_BYTES, pre_a, pre_b, acc);

            asm volatile("cp.async.wait_group 2;" ::: "memory");  // ms=61
            __syncthreads();
            mma_step(sbase + 1u * STAGE_BYTES, pre_a, pre_b, acc);

            asm volatile("cp.async.wait_group 1;" ::: "memory");  // ms=62
            __syncthreads();
            mma_step(sbase + 2u * STAGE_BYTES, pre_a, pre_b, acc);

            asm volatile("cp.async.wait_group 0;" ::: "memory");  // ms=63
            __syncthreads();
            mma_step(sbase + 3u * STAGE_BYTES, pre_a, pre_b, acc);
        }

        // epilogue: store split-K partial
        float* G = g_covp[split];
        #pragma unroll
        for (int mt = 0; mt < 4; mt++) {
            int gr0 = i0 + wm * 64 + mt * 16 + (lane >> 2);
            #pragma unroll
            for (int nt = 0; nt < 4; nt++) {
                int gc = j0 + wn * 32 + nt * 8 + (lane & 3) * 2;
                float* p0 = G + (size_t)gr0 * CF + gc;
                float* p1 = G + (size_t)(gr0 + 8) * CF + gc;
                *(float2*)p0 = make_float2(acc[mt * 4 + nt][0], acc[mt * 4 + nt][1]);
                *(float2*)p1 = make_float2(acc[mt * 4 + nt][2], acc[mt * 4 + nt][3]);
            }
        }
    } else {
        // ortho: dynamic loop (10 steps, minor cost)
        int load_step = 0;
        #pragma unroll
        for (; load_step < STAGES - 1; load_step++) {
            issue_loads(sbase + (uint32_t)load_step * STAGE_BYTES,
                        gA0 + load_step * 128, gB0 + load_step * 128, ld, tid);
            asm volatile("cp.async.commit_group;" ::: "memory");
        }
        for (int ms = 0; ms < NSTEP_ORT; ms++) {
            if (ms + 3 <= NSTEP_ORT)      asm volatile("cp.async.wait_group 2;" ::: "memory");
            else if (ms + 2 == NSTEP_ORT) asm volatile("cp.async.wait_group 1;" ::: "memory");
            else                          asm volatile("cp.async.wait_group 0;" ::: "memory");
            __syncthreads();
            if (load_step < NSTEP_ORT) {
                issue_loads(sbase + (uint32_t)(load_step % STAGES) * STAGE_BYTES,
                            gA0 + load_step * 128, gB0 + load_step * 128, ld, tid);
                asm volatile("cp.async.commit_group;" ::: "memory");
                load_step++;
            }
            mma_step(sbase + (uint32_t)(ms % STAGES) * STAGE_BYTES, pre_a, pre_b, acc);
        }

        float lsum = 0.f;
        #pragma unroll
        for (int mt = 0; mt < 4; mt++) {
            int gr0 = i0 + wm * 64 + mt * 16 + (lane >> 2);
            #pragma unroll
            for (int nt = 0; nt < 4; nt++) {
                int gc = j0 + wn * 32 + nt * 8 + (lane & 3) * 2;
                #pragma unroll
                for (int e = 0; e < 4; e++) {
                    int gr = gr0 + (e >> 1) * 8;
                    int gcc = gc + (e & 1);
                    if (gr < NCLS && gcc < NCLS) {
                        float d = fmaf(acc[mt * 4 + nt][e], WSCALE2_INV, -(gr == gcc ? 1.f : 0.f));
                        lsum = fmaf(d, d, lsum);
                    }
                }
            }
        }
        lsum = warpSum(lsum);
        __shared__ float red[8];
        if (lane == 0) red[wid] = lsum;
        __syncthreads();
        if (tid == 0) {
            float a = 0.f;
            #pragma unroll
            for (int i = 0; i < 8; i++) a += red[i];
            float w = (ti == tj) ? 1.f : 2.f;
            g_otp[t] = (double)(a * w);
        }
    }
}

// ---------------- cov loss reduce (pair-balanced, 512 blocks) -------------
__global__ __launch_bounds__(256) void k_covred() {
    __shared__ double swk[8];
    const float invB = 1.0f / (float)B_ROWS;
    int tid = threadIdx.x;
    double local = 0.0;
    for (int pr = blockIdx.x; pr < CF / 2; pr += NB_CR) {
        #pragma unroll
        for (int h = 0; h < 2; h++) {
            int r = h ? (CF - 1 - pr) : pr;
            float mur = g_musum[r] * invB;
            const float* row0 = &g_covp[0][(size_t)r * CF];
            const float* row1 = &g_covp[1][(size_t)r * CF];
            for (int c = tid; c <= r; c += 256) {
                float v = row0[c] + row1[c];
                float muc = g_musum[c] * invB;
                float cov = fmaf(v, invB, -mur * muc);
                float d = cov - (r == c ? 1.f : 0.f);
                float wgt = (c < r) ? 2.f : 1.f;
                local += (double)(wgt * d * d);
            }
        }
    }
    #pragma unroll
    for (int o = 16; o; o >>= 1) local += __shfl_xor_sync(0xffffffffu, local, o);
    if ((tid & 31) == 0) swk[tid >> 5] = local;
    __syncthreads();
    if (tid == 0) {
        double a = 0.0;
        #pragma unroll
        for (int i = 0; i < 8; i++) a += swk[i];
        g_cvp[blockIdx.x] = a;
    }
}

// ---------------- finalize ----------------
__global__ void k_final(float* out) {
    __shared__ double sred[8][6];
    int tid = threadIdx.x, lane = tid & 31, wid = tid >> 5;
    double nll = 0, l1 = 0, l2q = 0, kl = 0, cov = 0, ort = 0;
    for (int i = tid; i < NB_N;  i += 256) nll += (double)g_pn[i];
    for (int i = tid; i < NB_W;  i += 256) { l1 += (double)g_p1[i]; l2q += (double)g_p2[i]; }
    for (int i = tid; i < NB_F;  i += 256) kl  += (double)g_klp2[i];
    for (int i = tid; i < NB_CR; i += 256) cov += g_cvp[i];
    for (int i = tid; i < NT_ORT; i += 256) ort += g_otp[i];
    #pragma unroll
    for (int o = 16; o; o >>= 1) {
        nll += __shfl_xor_sync(0xffffffffu, nll, o);
        l1  += __shfl_xor_sync(0xffffffffu, l1, o);
        l2q += __shfl_xor_sync(0xffffffffu, l2q, o);
        kl  += __shfl_xor_sync(0xffffffffu, kl, o);
        cov += __shfl_xor_sync(0xffffffffu, cov, o);
        ort += __shfl_xor_sync(0xffffffffu, ort, o);
    }
    if (lane == 0) {
        sred[wid][0] = nll; sred[wid][1] = l1; sred[wid][2] = l2q;
        sred[wid][3] = kl;  sred[wid][4] = cov; sred[wid][5] = ort;
    }
    __syncthreads();
    if (tid == 0) {
        double a[6] = {0, 0, 0, 0, 0, 0};
        for (int i = 0; i < 8; i++)
            for (int j = 0; j < 6; j++) a[j] += sred[i][j];
        double loss = -a[0] / (double)B_ROWS
                    + 0.2 * (a[3] / (double)B_ROWS)
                    + 0.2 * a[4]
                    + 0.1 * a[5]
                    + 0.1 * a[1]
                    + 0.1 * sqrt(a[2]);
        out[0] = (float)loss;
    }
}

// ---------------- launch ----------------
extern "C" void kernel_launch(void* const* d_in, const int* in_sizes, int n_in,
                              void* d_out, int out_size) {
    const float* out_lp = nullptr;
    const void*  tgt = nullptr;
    const float* W = nullptr;
    const float* F = nullptr;
    for (int i = 0; i < n_in; i++) {
        long long sz = in_sizes[i];
        if (sz == (long long)B_ROWS * NCLS) out_lp = (const float*)d_in[i];
        else if (sz == B_ROWS)              tgt   = d_in[i];
        else if (sz == (long long)NCLS * CF) W    = (const float*)d_in[i];
        else if (sz == (long long)B_ROWS * CF) F  = (const float*)d_in[i];
    }
    if (!out_lp || !tgt || !W || !F) return;

    static int smem_set = 0;
    if (!smem_set) {
        cudaFuncSetAttribute(k_mma3, cudaFuncAttributeMaxDynamicSharedMemorySize, SMEM_MMA);
        smem_set = 1;
    }

    k_pre<<<NB_W + NB_N, 256>>>(W, out_lp, tgt);            // 1
    k_fpass<<<NB_F, 256>>>(F);                              // 2
    k_mma3<<<SPLITC * NT_COV + NT_ORT, 256, SMEM_MMA>>>();  // 3
    k_covred<<<NB_CR, 256>>>();                             // 4
    k_final<<<1, 256>>>((float*)d_out);                     // 5
}

// round 16
// speedup vs baseline: 1.0384x; 1.0384x over previous
#include <cuda_runtime.h>
#include <cuda_bf16.h>
#include <cuda_fp8.h>
#include <math.h>
#include <stdint.h>

#define B_ROWS 16384
#define NCLS   1000
#define CF     1280
#define NPAD   1024

#define NT_COV 55                 // 128x128 lower-tri tiles (split-K 2)
#define NT_ORT 36                 // 128x128 lower-tri tiles
#define SPLITC 2
#define KSPLIT (B_ROWS / SPLITC)  // 8192
#define NSTEP_COV (KSPLIT / 128)  // 64
#define NSTEP_ORT (CF / 128)      // 10

#define STAGES      4
#define STAGE_BYTES 32768
#define SMEM_MMA    (STAGES * STAGE_BYTES)

#define WSCALE 64.0f
#define WSCALE2_INV (1.0f / 4096.0f)

#define NB_W   384
#define NB_N   128
#define NB_F   (B_ROWS / 32)      // 512
#define NB_CR  512

// ---------------- device scratch ----------------
__device__ float  g_musum[CF];
__device__ float  g_p1[NB_W], g_p2[NB_W];
__device__ float  g_pn[NB_N];
__device__ float  g_klp2[NB_F];
__device__ double g_cvp[NB_CR];
__device__ double g_otp[NT_ORT];
__device__ __align__(256) uint8_t g_Ft8[CF][B_ROWS];
__device__ __align__(256) uint8_t g_Wb8[NPAD][CF];
__device__ float g_covp[SPLITC][CF * CF];

// ---------------- helpers ----------------
__device__ __forceinline__ float warpSum(float v) {
    #pragma unroll
    for (int o = 16; o; o >>= 1) v += __shfl_xor_sync(0xffffffffu, v, o);
    return v;
}
__device__ __forceinline__ uint32_t smem_u32(const void* p) {
    uint32_t a;
    asm("{ .reg .u64 t; cvta.to.shared.u64 t, %1; cvt.u32.u64 %0, t; }" : "=r"(a) : "l"(p));
    return a;
}
__device__ __forceinline__ uint32_t sw128(uint32_t off) {
    return off ^ ((off >> 3) & 0x70);
}
__device__ __forceinline__ void cp16(uint32_t saddr, const void* g) {
    asm volatile("cp.async.cg.shared.global [%0], [%1], 16;" :: "r"(saddr), "l"(g) : "memory");
}
__device__ __forceinline__ void ldsm4(uint32_t* r, uint32_t addr) {
    asm volatile("ldmatrix.sync.aligned.m8n8.x4.shared.b16 {%0,%1,%2,%3}, [%4];"
                 : "=r"(r[0]), "=r"(r[1]), "=r"(r[2]), "=r"(r[3]) : "r"(addr));
}
__device__ __forceinline__ void mma_fp8(float* d, const uint32_t* a, uint32_t b0, uint32_t b1) {
    asm volatile(
        "mma.sync.aligned.m16n8k32.row.col.f32.e4m3.e4m3.f32 "
        "{%0,%1,%2,%3}, {%4,%5,%6,%7}, {%8,%9}, {%0,%1,%2,%3};"
        : "+f"(d[0]), "+f"(d[1]), "+f"(d[2]), "+f"(d[3])
        : "r"(a[0]), "r"(a[1]), "r"(a[2]), "r"(a[3]), "r"(b0), "r"(b1));
}
__device__ __forceinline__ uint32_t pack4_e4m3(float a0, float a1, float a2, float a3) {
    uint16_t lo, hi;
    asm("cvt.rn.satfinite.e4m3x2.f32 %0, %1, %2;" : "=h"(lo) : "f"(a1), "f"(a0));
    asm("cvt.rn.satfinite.e4m3x2.f32 %0, %1, %2;" : "=h"(hi) : "f"(a3), "f"(a2));
    return (uint32_t)lo | ((uint32_t)hi << 16);
}

// ---------------- k_pre: wconv + nll + musum-zero ----------------
__global__ __launch_bounds__(256) void k_pre(const float* __restrict__ W,
                                             const float* __restrict__ out,
                                             const void* __restrict__ tgtraw) {
    int tid = threadIdx.x;
    if (blockIdx.x < NB_W) {
        __shared__ float s1[8], s2[8];
        int gid = blockIdx.x * 256 + tid;
        int stride = NB_W * 256;
        float a = 0.f, q = 0.f;
        const int nf4 = NCLS * CF / 4;
        for (int i = gid; i < nf4; i += stride) {
            float4 w = *((const float4*)W + i);
            a += (fabsf(w.x) + fabsf(w.y)) + (fabsf(w.z) + fabsf(w.w));
            q = fmaf(w.x, w.x, fmaf(w.y, w.y, fmaf(w.z, w.z, fmaf(w.w, w.w, q))));
            *(uint32_t*)&g_Wb8[0][i * 4] = pack4_e4m3(w.x * WSCALE, w.y * WSCALE,
                                                      w.z * WSCALE, w.w * WSCALE);
        }
        const int padw = (NPAD - NCLS) * CF / 4;
        for (int i = gid; i < padw; i += stride)
            *((uint32_t*)&g_Wb8[NCLS][0] + i) = 0u;
        a = warpSum(a); q = warpSum(q);
        if ((tid & 31) == 0) { s1[tid >> 5] = a; s2[tid >> 5] = q; }
        __syncthreads();
        if (tid == 0) {
            float aa = 0.f, qq = 0.f;
            #pragma unroll
            for (int i = 0; i < 8; i++) { aa += s1[i]; qq += s2[i]; }
            g_p1[blockIdx.x] = aa;
            g_p2[blockIdx.x] = qq;
        }
    } else {
        __shared__ float swk[8];
        __shared__ int s_is64;
        const int* t32 = (const int*)tgtraw;
        int b0 = blockIdx.x - NB_W;
        int zi = b0 * 256 + tid;
        if (zi < CF) g_musum[zi] = 0.f;
        if (tid == 0) {
            int all0 = 1;
            #pragma unroll
            for (int k = 0; k < 32; k++) all0 &= (t32[2 * k + 1] == 0);
            s_is64 = all0;
        }
        __syncthreads();
        int is64 = s_is64;
        int gid = b0 * 256 + tid;
        int stride = NB_N * 256;
        float v = 0.f;
        for (int b = gid; b < B_ROWS; b += stride) {
            int idx = is64 ? (int)((const long long*)tgtraw)[b] : t32[b];
            idx = min(max(idx, 0), NCLS - 1);
            v += out[(size_t)b * NCLS + idx];
        }
        v = warpSum(v);
        if ((tid & 31) == 0) swk[tid >> 5] = v;
        __syncthreads();
        if (tid == 0) {
            float aa = 0.f;
            #pragma unroll
            for (int i = 0; i < 8; i++) aa += swk[i];
            g_pn[b0] = aa;
        }
    }
}

// ---------------- fused F pass: paired chunks ----------------
__global__ __launch_bounds__(256) void k_fpass(const float* __restrict__ F) {
    __shared__ float ts[2][2][32][33];
    __shared__ float srow[32];
    int r0 = blockIdx.x * 32;
    int t = threadIdx.x;
    int lane = t & 31;
    int r  = t >> 3;
    int u  = t & 7;
    int c4 = u * 4;
    int cc = t >> 3;
    int rs = u * 4;

    const float4* frow = (const float4*)(F + (size_t)(r0 + r) * CF);
    float sx = 0.f, se = 0.f, sex = 0.f;

    for (int p = 0; p < 20; p++) {
        int pb = p & 1;
        float4 v0 = frow[(2 * p) * 8 + u];
        float4 v1 = frow[(2 * p + 1) * 8 + u];

        float e0 = __expf(v0.x), e1 = __expf(v0.y), e2 = __expf(v0.z), e3 = __expf(v0.w);
        sx += (v0.x + v0.y) + (v0.z + v0.w);
        se += (e0 + e1) + (e2 + e3);
        sex = fmaf(e0, v0.x, fmaf(e1, v0.y, fmaf(e2, v0.z, fmaf(e3, v0.w, sex))));
        ts[pb][0][r][c4 + 0] = v0.x;
        ts[pb][0][r][c4 + 1] = v0.y;
        ts[pb][0][r][c4 + 2] = v0.z;
        ts[pb][0][r][c4 + 3] = v0.w;

        float f0 = __expf(v1.x), f1 = __expf(v1.y), f2 = __expf(v1.z), f3 = __expf(v1.w);
        sx += (v1.x + v1.y) + (v1.z + v1.w);
        se += (f0 + f1) + (f2 + f3);
        sex = fmaf(f0, v1.x, fmaf(f1, v1.y, fmaf(f2, v1.z, fmaf(f3, v1.w, sex))));
        ts[pb][1][r][c4 + 0] = v1.x;
        ts[pb][1][r][c4 + 1] = v1.y;
        ts[pb][1][r][c4 + 2] = v1.z;
        ts[pb][1][r][c4 + 3] = v1.w;

        __syncthreads();

        #pragma unroll
        for (int h = 0; h < 2; h++) {
            int ch = 2 * p + h;
            float a0 = ts[pb][h][rs + 0][cc];
            float a1 = ts[pb][h][rs + 1][cc];
            float a2 = ts[pb][h][rs + 2][cc];
            float a3 = ts[pb][h][rs + 3][cc];
            float cs = (a0 + a1) + (a2 + a3);
            cs += __shfl_down_sync(0xffffffffu, cs, 4);
            cs += __shfl_down_sync(0xffffffffu, cs, 2);
            cs += __shfl_down_sync(0xffffffffu, cs, 1);
            if ((lane & 7) == 0) atomicAdd(&g_musum[ch * 32 + cc], cs);
            *(uint32_t*)&g_Ft8[ch * 32 + cc][r0 + rs] = pack4_e4m3(a0, a1, a2, a3);
        }
    }

    sx  += __shfl_down_sync(0xffffffffu, sx, 4);
    sx  += __shfl_down_sync(0xffffffffu, sx, 2);
    sx  += __shfl_down_sync(0xffffffffu, sx, 1);
    se  += __shfl_down_sync(0xffffffffu, se, 4);
    se  += __shfl_down_sync(0xffffffffu, se, 2);
    se  += __shfl_down_sync(0xffffffffu, se, 1);
    sex += __shfl_down_sync(0xffffffffu, sex, 4);
    sex += __shfl_down_sync(0xffffffffu, sex, 2);
    sex += __shfl_down_sync(0xffffffffu, sex, 1);
    if ((lane & 7) == 0) srow[r] = (float)CF * (sex / se) - sx;
    __syncthreads();
    if (t < 32) {
        float rv = srow[t];
        rv = warpSum(rv);
        if (t == 0) g_klp2[blockIdx.x] = rv;
    }
}

// ---------------- fp8 MMA: 256 threads, 8 warps, 64x32 warp tiles ---------
__device__ __forceinline__ void issue_loads(uint32_t tbase, const uint8_t* gA,
                                            const uint8_t* gB, int ld, int tid) {
    #pragma unroll
    for (int i = 0; i < 4; i++) {
        int q = tid + i * 256;            // 0..1023
        int r = q >> 3, u = q & 7;
        uint32_t so = sw128((uint32_t)(r * 128 + u * 16));
        cp16(tbase + so, gA + (size_t)r * ld + u * 16);
        cp16(tbase + 16384 + so, gB + (size_t)r * ld + u * 16);
    }
}

__global__ __launch_bounds__(256, 1) void k_mma3() {
    extern __shared__ char dsm[];
    uint32_t sbase = smem_u32(dsm);
    int tid = threadIdx.x, wid = tid >> 5, lane = tid & 31;
    int bid = blockIdx.x;

    bool is_cov = bid < SPLITC * NT_COV;
    int split = is_cov ? (bid >= NT_COV ? 1 : 0) : 0;
    int t = is_cov ? (bid - split * NT_COV) : (bid - SPLITC * NT_COV);
    int ti = 0;
    while ((ti + 1) * (ti + 2) / 2 <= t) ++ti;
    int tj = t - ti * (ti + 1) / 2;
    int i0 = ti * 128, j0 = tj * 128;

    const uint8_t* src = is_cov ? &g_Ft8[0][0] : &g_Wb8[0][0];
    const int ld = is_cov ? B_ROWS : CF;
    const int nstep = is_cov ? NSTEP_COV : NSTEP_ORT;
    const size_t koff = is_cov ? (size_t)split * KSPLIT : 0;

    const uint8_t* gA0 = src + (size_t)i0 * ld + koff;
    const uint8_t* gB0 = src + (size_t)j0 * ld + koff;

    int wm = wid >> 2, wn = wid & 3;   // warp tile 64(m) x 32(n)

    float acc[16][4];
    #pragma unroll
    for (int i = 0; i < 16; i++)
        #pragma unroll
        for (int j = 0; j < 4; j++) acc[i][j] = 0.f;

    // swizzle-folded fragment bases (128B rows)
    uint32_t pre_a[4], pre_b[2];
    {
        uint32_t arow = (uint32_t)(wm * 64 + (lane & 15));
        uint32_t ahi  = (uint32_t)((lane >> 4) * 16);
        #pragma unroll
        for (int mt = 0; mt < 4; mt++) {
            uint32_t rr = arow + mt * 16;
            pre_a[mt] = rr * 128 + (ahi ^ ((rr * 16) & 0x70));
        }
        uint32_t brow = (uint32_t)(wn * 32 + (((lane >> 4) & 1) << 3) + (lane & 7));
        uint32_t bhi  = (uint32_t)(((lane >> 3) & 1) * 16);
        #pragma unroll
        for (int p = 0; p < 2; p++) {
            uint32_t rr = brow + p * 16;
            pre_b[p] = 16384u + rr * 128 + (bhi ^ ((rr * 16) & 0x70));
        }
    }

    int load_step = 0;
    #pragma unroll
    for (; load_step < STAGES - 1; load_step++) {
        issue_loads(sbase + (uint32_t)load_step * STAGE_BYTES,
                    gA0 + load_step * 128, gB0 + load_step * 128, ld, tid);
        asm volatile("cp.async.commit_group;" ::: "memory");
    }

    for (int ms = 0; ms < nstep; ms++) {
        if (ms + 3 <= nstep)      asm volatile("cp.async.wait_group 2;" ::: "memory");
        else if (ms + 2 == nstep) asm volatile("cp.async.wait_group 1;" ::: "memory");
        else                      asm volatile("cp.async.wait_group 0;" ::: "memory");
        __syncthreads();

        if (load_step < nstep) {
            issue_loads(sbase + (uint32_t)(load_step % STAGES) * STAGE_BYTES,
                        gA0 + load_step * 128, gB0 + load_step * 128, ld, tid);
            asm volatile("cp.async.commit_group;" ::: "memory");
            load_step++;
        }

        uint32_t stbase = sbase + (uint32_t)(ms % STAGES) * STAGE_BYTES;

        #pragma unroll
        for (int ks = 0; ks < 4; ks++) {
            uint32_t kx = (uint32_t)(ks << 5);
            uint32_t bfr[2][4];
            #pragma unroll
            for (int p = 0; p < 2; p++)
                ldsm4(bfr[p], stbase + (pre_b[p] ^ kx));
            #pragma unroll
            for (int mt = 0; mt < 4; mt++) {
                uint32_t afr[4];
                ldsm4(afr, stbase + (pre_a[mt] ^ kx));
                #pragma unroll
                for (int nt = 0; nt < 4; nt++)
                    mma_fp8(acc[mt * 4 + nt], afr,
                            bfr[nt >> 1][(nt & 1) * 2], bfr[nt >> 1][(nt & 1) * 2 + 1]);
            }
        }
    }

    // ---------------- epilogue ----------------
    if (is_cov) {
        float* G = g_covp[split];
        #pragma unroll
        for (int mt = 0; mt < 4; mt++) {
            int gr0 = i0 + wm * 64 + mt * 16 + (lane >> 2);
            #pragma unroll
            for (int nt = 0; nt < 4; nt++) {
                int gc = j0 + wn * 32 + nt * 8 + (lane & 3) * 2;
                float* p0 = G + (size_t)gr0 * CF + gc;
                float* p1 = G + (size_t)(gr0 + 8) * CF + gc;
                *(float2*)p0 = make_float2(acc[mt * 4 + nt][0], acc[mt * 4 + nt][1]);
                *(float2*)p1 = make_float2(acc[mt * 4 + nt][2], acc[mt * 4 + nt][3]);
            }
        }
    } else {
        float lsum = 0.f;
        #pragma unroll
        for (int mt = 0; mt < 4; mt++) {
            int gr0 = i0 + wm * 64 + mt * 16 + (lane >> 2);
            #pragma unroll
            for (int nt = 0; nt < 4; nt++) {
                int gc = j0 + wn * 32 + nt * 8 + (lane & 3) * 2;
                #pragma unroll
                for (int e = 0; e < 4; e++) {
                    int gr = gr0 + (e >> 1) * 8;
                    int gcc = gc + (e & 1);
                    if (gr < NCLS && gcc < NCLS) {
                        float d = fmaf(acc[mt * 4 + nt][e], WSCALE2_INV, -(gr == gcc ? 1.f : 0.f));
                        lsum = fmaf(d, d, lsum);
                    }
                }
            }
        }
        lsum = warpSum(lsum);
        __shared__ float red[8];
        if (lane == 0) red[wid] = lsum;
        __syncthreads();
        if (tid == 0) {
            float a = 0.f;
            #pragma unroll
            for (int i = 0; i < 8; i++) a += red[i];
            float w = (ti == tj) ? 1.f : 2.f;
            g_otp[t] = (double)(a * w);
        }
    }
}

// ---------------- cov loss reduce (pair-balanced, float4) -----------------
__global__ __launch_bounds__(256) void k_covred() {
    __shared__ double swk[8];
    const float invB = 1.0f / (float)B_ROWS;
    int tid = threadIdx.x;
    double local = 0.0;
    for (int pr = blockIdx.x; pr < CF / 2; pr += NB_CR) {
        #pragma unroll
        for (int h = 0; h < 2; h++) {
            int r = h ? (CF - 1 - pr) : pr;
            float mur = g_musum[r] * invB;
            const float4* row0 = (const float4*)&g_covp[0][(size_t)r * CF];
            const float4* row1 = (const float4*)&g_covp[1][(size_t)r * CF];
            const float4* mus  = (const float4*)g_musum;
            int n4 = (r + 1) >> 2;          // full quads with c+3 <= r
            float facc = 0.f;
            for (int i4 = tid; i4 < n4; i4 += 256) {
                float4 a = row0[i4];
                float4 b = row1[i4];
                float4 m = mus[i4];
                int c0 = i4 * 4;
                float v0 = fmaf(a.x + b.x, invB, -mur * (m.x * invB));
                float v1 = fmaf(a.y + b.y, invB, -mur * (m.y * invB));
                float v2 = fmaf(a.z + b.z, invB, -mur * (m.z * invB));
                float v3 = fmaf(a.w + b.w, invB, -mur * (m.w * invB));
                float d0 = v0 - (c0 + 0 == r ? 1.f : 0.f);
                float d1 = v1 - (c0 + 1 == r ? 1.f : 0.f);
                float d2 = v2 - (c0 + 2 == r ? 1.f : 0.f);
                float d3 = v3 - (c0 + 3 == r ? 1.f : 0.f);
                float w0 = (c0 + 0 < r) ? 2.f : 1.f;
                float w1 = (c0 + 1 < r) ? 2.f : 1.f;
                float w2 = (c0 + 2 < r) ? 2.f : 1.f;
                float w3 = (c0 + 3 < r) ? 2.f : 1.f;
                facc += w0 * d0 * d0 + w1 * d1 * d1 + w2 * d2 * d2 + w3 * d3 * d3;
            }
            // remainder columns [n4*4, r]
            int rem0 = n4 * 4;
            if (tid <= r - rem0) {
                int c = rem0 + tid;
                float v = g_covp[0][(size_t)r * CF + c] + g_covp[1][(size_t)r * CF + c];
                float muc = g_musum[c] * invB;
                float cov = fmaf(v, invB, -mur * muc);
                float d = cov - (r == c ? 1.f : 0.f);
                float wgt = (c < r) ? 2.f : 1.f;
                facc += wgt * d * d;
            }
            local += (double)facc;
        }
    }
    #pragma unroll
    for (int o = 16; o; o >>= 1) local += __shfl_xor_sync(0xffffffffu, local, o);
    if ((tid & 31) == 0) swk[tid >> 5] = local;
    __syncthreads();
    if (tid == 0) {
        double a = 0.0;
        #pragma unroll
        for (int i = 0; i < 8; i++) a += swk[i];
        g_cvp[blockIdx.x] = a;
    }
}

// ---------------- finalize ----------------
__global__ void k_final(float* out) {
    __shared__ double sred[8][6];
    int tid = threadIdx.x, lane = tid & 31, wid = tid >> 5;
    double nll = 0, l1 = 0, l2q = 0, kl = 0, cov = 0, ort = 0;
    for (int i = tid; i < NB_N;  i += 256) nll += (double)g_pn[i];
    for (int i = tid; i < NB_W;  i += 256) { l1 += (double)g_p1[i]; l2q += (double)g_p2[i]; }
    for (int i = tid; i < NB_F;  i += 256) kl  += (double)g_klp2[i];
    for (int i = tid; i < NB_CR; i += 256) cov += g_cvp[i];
    for (int i = tid; i < NT_ORT; i += 256) ort += g_otp[i];
    #pragma unroll
    for (int o = 16; o; o >>= 1) {
        nll += __shfl_xor_sync(0xffffffffu, nll, o);
        l1  += __shfl_xor_sync(0xffffffffu, l1, o);
        l2q += __shfl_xor_sync(0xffffffffu, l2q, o);
        kl  += __shfl_xor_sync(0xffffffffu, kl, o);
        cov += __shfl_xor_sync(0xffffffffu, cov, o);
        ort += __shfl_xor_sync(0xffffffffu, ort, o);
    }
    if (lane == 0) {
        sred[wid][0] = nll; sred[wid][1] = l1; sred[wid][2] = l2q;
        sred[wid][3] = kl;  sred[wid][4] = cov; sred[wid][5] = ort;
    }
    __syncthreads();
    if (tid == 0) {
        double a[6] = {0, 0, 0, 0, 0, 0};
        for (int i = 0; i < 8; i++)
            for (int j = 0; j < 6; j++) a[j] += sred[i][j];
        double loss = -a[0] / (double)B_ROWS
                    + 0.2 * (a[3] / (double)B_ROWS)
                    + 0.2 * a[4]
                    + 0.1 * a[5]
                    + 0.1 * a[1]
                    + 0.1 * sqrt(a[2]);
        out[0] = (float)loss;
    }
}

// ---------------- launch ----------------
extern "C" void kernel_launch(void* const* d_in, const int* in_sizes, int n_in,
                              void* d_out, int out_size) {
    const float* out_lp = nullptr;
    const void*  tgt = nullptr;
    const float* W = nullptr;
    const float* F = nullptr;
    for (int i = 0; i < n_in; i++) {
        long long sz = in_sizes[i];
        if (sz == (long long)B_ROWS * NCLS) out_lp = (const float*)d_in[i];
        else if (sz == B_ROWS)              tgt   = d_in[i];
        else if (sz == (long long)NCLS * CF) W    = (const float*)d_in[i];
        else if (sz == (long long)B_ROWS * CF) F  = (const float*)d_in[i];
    }
    if (!out_lp || !tgt || !W || !F) return;

    static int smem_set = 0;
    if (!smem_set) {
        cudaFuncSetAttribute(k_mma3, cudaFuncAttributeMaxDynamicSharedMemorySize, SMEM_MMA);
        smem_set = 1;
    }

    k_pre<<<NB_W + NB_N, 256>>>(W, out_lp, tgt);            // 1
    k_fpass<<<NB_F, 256>>>(F);                              // 2
    k_mma3<<<SPLITC * NT_COV + NT_ORT, 256, SMEM_MMA>>>();  // 3
    k_covred<<<NB_CR, 256>>>();                             // 4
    k_final<<<1, 256>>>((float*)d_out);                     // 5
}

// round 17
// speedup vs baseline: 1.0638x; 1.0245x over previous
#include <cuda_runtime.h>
#include <cuda_bf16.h>
#include <cuda_fp8.h>
#include <math.h>
#include <stdint.h>

#define B_ROWS 16384
#define NCLS   1000
#define CF     1280
#define NPAD   1024

#define NT_COV 55                 // 128x128 lower-tri tiles (split-K 2)
#define NT_ORT 36                 // 128x128 lower-tri tiles
#define SPLITC 2
#define KSPLIT (B_ROWS / SPLITC)  // 8192
#define NSTEP_COV (KSPLIT / 128)  // 64
#define NSTEP_ORT (CF / 128)      // 10

#define STAGES      4
#define STAGE_BYTES 32768
#define SMEM_MMA    (STAGES * STAGE_BYTES)

#define WSCALE 64.0f
#define WSCALE2_INV (1.0f / 4096.0f)

#define NB_F   512                // fpass blocks
#define NB_W   384                // wconv blocks
#define NB_N   128                // nll blocks
#define NB_PF  (NB_F + NB_W + NB_N)
#define NB_CR  512

// ---------------- device scratch ----------------
__device__ float  g_musum[CF];                 // zeroed by memset node
__device__ float  g_p1[NB_W], g_p2[NB_W];
__device__ float  g_pn[NB_N];
__device__ float  g_klp2[NB_F];
__device__ double g_cvp[NB_CR];
__device__ double g_otp[NT_ORT];
__device__ __align__(256) uint8_t g_Ft8[CF][B_ROWS];
__device__ __align__(256) uint8_t g_Wb8[NPAD][CF];
__device__ float g_covp[SPLITC][CF * CF];

// ---------------- helpers ----------------
__device__ __forceinline__ float warpSum(float v) {
    #pragma unroll
    for (int o = 16; o; o >>= 1) v += __shfl_xor_sync(0xffffffffu, v, o);
    return v;
}
__device__ __forceinline__ uint32_t smem_u32(const void* p) {
    uint32_t a;
    asm("{ .reg .u64 t; cvta.to.shared.u64 t, %1; cvt.u32.u64 %0, t; }" : "=r"(a) : "l"(p));
    return a;
}
__device__ __forceinline__ uint32_t sw128(uint32_t off) {
    return off ^ ((off >> 3) & 0x70);
}
__device__ __forceinline__ void cp16(uint32_t saddr, const void* g) {
    asm volatile("cp.async.cg.shared.global [%0], [%1], 16;" :: "r"(saddr), "l"(g) : "memory");
}
__device__ __forceinline__ void ldsm4(uint32_t* r, uint32_t addr) {
    asm volatile("ldmatrix.sync.aligned.m8n8.x4.shared.b16 {%0,%1,%2,%3}, [%4];"
                 : "=r"(r[0]), "=r"(r[1]), "=r"(r[2]), "=r"(r[3]) : "r"(addr));
}
__device__ __forceinline__ void mma_fp8(float* d, const uint32_t* a, uint32_t b0, uint32_t b1) {
    asm volatile(
        "mma.sync.aligned.m16n8k32.row.col.f32.e4m3.e4m3.f32 "
        "{%0,%1,%2,%3}, {%4,%5,%6,%7}, {%8,%9}, {%0,%1,%2,%3};"
        : "+f"(d[0]), "+f"(d[1]), "+f"(d[2]), "+f"(d[3])
        : "r"(a[0]), "r"(a[1]), "r"(a[2]), "r"(a[3]), "r"(b0), "r"(b1));
}
__device__ __forceinline__ uint32_t pack4_e4m3(float a0, float a1, float a2, float a3) {
    uint16_t lo, hi;
    asm("cvt.rn.satfinite.e4m3x2.f32 %0, %1, %2;" : "=h"(lo) : "f"(a1), "f"(a0));
    asm("cvt.rn.satfinite.e4m3x2.f32 %0, %1, %2;" : "=h"(hi) : "f"(a3), "f"(a2));
    return (uint32_t)lo | ((uint32_t)hi << 16);
}

// ---------------- k_pf: fpass + wconv + nll (one grid; musum pre-zeroed) --
__global__ __launch_bounds__(256) void k_pf(const float* __restrict__ F,
                                            const float* __restrict__ W,
                                            const float* __restrict__ out,
                                            const void* __restrict__ tgtraw) {
    int t = threadIdx.x;
    int bid = blockIdx.x;

    if (bid < NB_F) {
        // ---- fused F pass: KL + colsum + transpose->e4m3 (paired chunks) ----
        __shared__ float ts[2][2][32][33];
        __shared__ float srow[32];
        int r0 = bid * 32;
        int lane = t & 31;
        int r  = t >> 3;
        int u  = t & 7;
        int c4 = u * 4;
        int cc = t >> 3;
        int rs = u * 4;

        const float4* frow = (const float4*)(F + (size_t)(r0 + r) * CF);
        float sx = 0.f, se = 0.f, sex = 0.f;

        for (int p = 0; p < 20; p++) {
            int pb = p & 1;
            float4 v0 = frow[(2 * p) * 8 + u];
            float4 v1 = frow[(2 * p + 1) * 8 + u];

            float e0 = __expf(v0.x), e1 = __expf(v0.y), e2 = __expf(v0.z), e3 = __expf(v0.w);
            sx += (v0.x + v0.y) + (v0.z + v0.w);
            se += (e0 + e1) + (e2 + e3);
            sex = fmaf(e0, v0.x, fmaf(e1, v0.y, fmaf(e2, v0.z, fmaf(e3, v0.w, sex))));
            ts[pb][0][r][c4 + 0] = v0.x;
            ts[pb][0][r][c4 + 1] = v0.y;
            ts[pb][0][r][c4 + 2] = v0.z;
            ts[pb][0][r][c4 + 3] = v0.w;

            float f0 = __expf(v1.x), f1 = __expf(v1.y), f2 = __expf(v1.z), f3 = __expf(v1.w);
            sx += (v1.x + v1.y) + (v1.z + v1.w);
            se += (f0 + f1) + (f2 + f3);
            sex = fmaf(f0, v1.x, fmaf(f1, v1.y, fmaf(f2, v1.z, fmaf(f3, v1.w, sex))));
            ts[pb][1][r][c4 + 0] = v1.x;
            ts[pb][1][r][c4 + 1] = v1.y;
            ts[pb][1][r][c4 + 2] = v1.z;
            ts[pb][1][r][c4 + 3] = v1.w;

            __syncthreads();

            #pragma unroll
            for (int h = 0; h < 2; h++) {
                int ch = 2 * p + h;
                float a0 = ts[pb][h][rs + 0][cc];
                float a1 = ts[pb][h][rs + 1][cc];
                float a2 = ts[pb][h][rs + 2][cc];
                float a3 = ts[pb][h][rs + 3][cc];
                float cs = (a0 + a1) + (a2 + a3);
                cs += __shfl_down_sync(0xffffffffu, cs, 4);
                cs += __shfl_down_sync(0xffffffffu, cs, 2);
                cs += __shfl_down_sync(0xffffffffu, cs, 1);
                if ((lane & 7) == 0) atomicAdd(&g_musum[ch * 32 + cc], cs);
                *(uint32_t*)&g_Ft8[ch * 32 + cc][r0 + rs] = pack4_e4m3(a0, a1, a2, a3);
            }
        }

        sx  += __shfl_down_sync(0xffffffffu, sx, 4);
        sx  += __shfl_down_sync(0xffffffffu, sx, 2);
        sx  += __shfl_down_sync(0xffffffffu, sx, 1);
        se  += __shfl_down_sync(0xffffffffu, se, 4);
        se  += __shfl_down_sync(0xffffffffu, se, 2);
        se  += __shfl_down_sync(0xffffffffu, se, 1);
        sex += __shfl_down_sync(0xffffffffu, sex, 4);
        sex += __shfl_down_sync(0xffffffffu, sex, 2);
        sex += __shfl_down_sync(0xffffffffu, sex, 1);
        if ((lane & 7) == 0) srow[r] = (float)CF * (sex / se) - sx;
        __syncthreads();
        if (t < 32) {
            float rv = srow[t];
            rv = warpSum(rv);
            if (t == 0) g_klp2[bid] = rv;
        }
    } else if (bid < NB_F + NB_W) {
        // ---- W convert + L1/L2 partials ----
        __shared__ float s1[8], s2[8];
        int b = bid - NB_F;
        int gid = b * 256 + t;
        int stride = NB_W * 256;
        float a = 0.f, q = 0.f;
        const int nf4 = NCLS * CF / 4;
        for (int i = gid; i < nf4; i += stride) {
            float4 w = *((const float4*)W + i);
            a += (fabsf(w.x) + fabsf(w.y)) + (fabsf(w.z) + fabsf(w.w));
            q = fmaf(w.x, w.x, fmaf(w.y, w.y, fmaf(w.z, w.z, fmaf(w.w, w.w, q))));
            *(uint32_t*)&g_Wb8[0][i * 4] = pack4_e4m3(w.x * WSCALE, w.y * WSCALE,
                                                      w.z * WSCALE, w.w * WSCALE);
        }
        const int padw = (NPAD - NCLS) * CF / 4;
        for (int i = gid; i < padw; i += stride)
            *((uint32_t*)&g_Wb8[NCLS][0] + i) = 0u;
        a = warpSum(a); q = warpSum(q);
        if ((t & 31) == 0) { s1[t >> 5] = a; s2[t >> 5] = q; }
        __syncthreads();
        if (t == 0) {
            float aa = 0.f, qq = 0.f;
            #pragma unroll
            for (int i = 0; i < 8; i++) { aa += s1[i]; qq += s2[i]; }
            g_p1[b] = aa;
            g_p2[b] = qq;
        }
    } else {
        // ---- nll gather (dtype-robust probe) ----
        __shared__ float swk[8];
        __shared__ int s_is64;
        const int* t32 = (const int*)tgtraw;
        int b0 = bid - NB_F - NB_W;
        if (t == 0) {
            int all0 = 1;
            #pragma unroll
            for (int k = 0; k < 32; k++) all0 &= (t32[2 * k + 1] == 0);
            s_is64 = all0;
        }
        __syncthreads();
        int is64 = s_is64;
        int gid = b0 * 256 + t;
        int stride = NB_N * 256;
        float v = 0.f;
        for (int b = gid; b < B_ROWS; b += stride) {
            int idx = is64 ? (int)((const long long*)tgtraw)[b] : t32[b];
            idx = min(max(idx, 0), NCLS - 1);
            v += out[(size_t)b * NCLS + idx];
        }
        v = warpSum(v);
        if ((t & 31) == 0) swk[t >> 5] = v;
        __syncthreads();
        if (t == 0) {
            float aa = 0.f;
            #pragma unroll
            for (int i = 0; i < 8; i++) aa += swk[i];
            g_pn[b0] = aa;
        }
    }
}

// ---------------- fp8 MMA: 256 threads, 8 warps, 64x32 warp tiles ---------
__device__ __forceinline__ void issue_loads(uint32_t tbase, const uint8_t* gA,
                                            const uint8_t* gB, int ld, int tid) {
    #pragma unroll
    for (int i = 0; i < 4; i++) {
        int q = tid + i * 256;            // 0..1023
        int r = q >> 3, u = q & 7;
        uint32_t so = sw128((uint32_t)(r * 128 + u * 16));
        cp16(tbase + so, gA + (size_t)r * ld + u * 16);
        cp16(tbase + 16384 + so, gB + (size_t)r * ld + u * 16);
    }
}

__global__ __launch_bounds__(256, 1) void k_mma3() {
    extern __shared__ char dsm[];
    uint32_t sbase = smem_u32(dsm);
    int tid = threadIdx.x, wid = tid >> 5, lane = tid & 31;
    int bid = blockIdx.x;

    bool is_cov = bid < SPLITC * NT_COV;
    int split = is_cov ? (bid >= NT_COV ? 1 : 0) : 0;
    int t = is_cov ? (bid - split * NT_COV) : (bid - SPLITC * NT_COV);
    int ti = 0;
    while ((ti + 1) * (ti + 2) / 2 <= t) ++ti;
    int tj = t - ti * (ti + 1) / 2;
    int i0 = ti * 128, j0 = tj * 128;

    const uint8_t* src = is_cov ? &g_Ft8[0][0] : &g_Wb8[0][0];
    const int ld = is_cov ? B_ROWS : CF;
    const int nstep = is_cov ? NSTEP_COV : NSTEP_ORT;
    const size_t koff = is_cov ? (size_t)split * KSPLIT : 0;

    const uint8_t* gA0 = src + (size_t)i0 * ld + koff;
    const uint8_t* gB0 = src + (size_t)j0 * ld + koff;

    int wm = wid >> 2, wn = wid & 3;   // warp tile 64(m) x 32(n)

    float acc[16][4];
    #pragma unroll
    for (int i = 0; i < 16; i++)
        #pragma unroll
        for (int j = 0; j < 4; j++) acc[i][j] = 0.f;

    // swizzle-folded fragment bases (128B rows)
    uint32_t pre_a[4], pre_b[2];
    {
        uint32_t arow = (uint32_t)(wm * 64 + (lane & 15));
        uint32_t ahi  = (uint32_t)((lane >> 4) * 16);
        #pragma unroll
        for (int mt = 0; mt < 4; mt++) {
            uint32_t rr = arow + mt * 16;
            pre_a[mt] = rr * 128 + (ahi ^ ((rr * 16) & 0x70));
        }
        uint32_t brow = (uint32_t)(wn * 32 + (((lane >> 4) & 1) << 3) + (lane & 7));
        uint32_t bhi  = (uint32_t)(((lane >> 3) & 1) * 16);
        #pragma unroll
        for (int p = 0; p < 2; p++) {
            uint32_t rr = brow + p * 16;
            pre_b[p] = 16384u + rr * 128 + (bhi ^ ((rr * 16) & 0x70));
        }
    }

    int load_step = 0;
    #pragma unroll
    for (; load_step < STAGES - 1; load_step++) {
        issue_loads(sbase + (uint32_t)load_step * STAGE_BYTES,
                    gA0 + load_step * 128, gB0 + load_step * 128, ld, tid);
        asm volatile("cp.async.commit_group;" ::: "memory");
    }

    for (int ms = 0; ms < nstep; ms++) {
        if (ms + 3 <= nstep)      asm volatile("cp.async.wait_group 2;" ::: "memory");
        else if (ms + 2 == nstep) asm volatile("cp.async.wait_group 1;" ::: "memory");
        else                      asm volatile("cp.async.wait_group 0;" ::: "memory");
        __syncthreads();

        if (load_step < nstep) {
            issue_loads(sbase + (uint32_t)(load_step % STAGES) * STAGE_BYTES,
                        gA0 + load_step * 128, gB0 + load_step * 128, ld, tid);
            asm volatile("cp.async.commit_group;" ::: "memory");
            load_step++;
        }

        uint32_t stbase = sbase + (uint32_t)(ms % STAGES) * STAGE_BYTES;

        #pragma unroll
        for (int ks = 0; ks < 4; ks++) {
            uint32_t kx = (uint32_t)(ks << 5);
            uint32_t bfr[2][4];
            #pragma unroll
            for (int p = 0; p < 2; p++)
                ldsm4(bfr[p], stbase + (pre_b[p] ^ kx));
            #pragma unroll
            for (int mt = 0; mt < 4; mt++) {
                uint32_t afr[4];
                ldsm4(afr, stbase + (pre_a[mt] ^ kx));
                #pragma unroll
                for (int nt = 0; nt < 4; nt++)
                    mma_fp8(acc[mt * 4 + nt], afr,
                            bfr[nt >> 1][(nt & 1) * 2], bfr[nt >> 1][(nt & 1) * 2 + 1]);
            }
        }
    }

    // ---------------- epilogue ----------------
    if (is_cov) {
        float* G = g_covp[split];
        #pragma unroll
        for (int mt = 0; mt < 4; mt++) {
            int gr0 = i0 + wm * 64 + mt * 16 + (lane >> 2);
            #pragma unroll
            for (int nt = 0; nt < 4; nt++) {
                int gc = j0 + wn * 32 + nt * 8 + (lane & 3) * 2;
                float* p0 = G + (size_t)gr0 * CF + gc;
                float* p1 = G + (size_t)(gr0 + 8) * CF + gc;
                *(float2*)p0 = make_float2(acc[mt * 4 + nt][0], acc[mt * 4 + nt][1]);
                *(float2*)p1 = make_float2(acc[mt * 4 + nt][2], acc[mt * 4 + nt][3]);
            }
        }
    } else {
        float lsum = 0.f;
        #pragma unroll
        for (int mt = 0; mt < 4; mt++) {
            int gr0 = i0 + wm * 64 + mt * 16 + (lane >> 2);
            #pragma unroll
            for (int nt = 0; nt < 4; nt++) {
                int gc = j0 + wn * 32 + nt * 8 + (lane & 3) * 2;
                #pragma unroll
                for (int e = 0; e < 4; e++) {
                    int gr = gr0 + (e >> 1) * 8;
                    int gcc = gc + (e & 1);
                    if (gr < NCLS && gcc < NCLS) {
                        float d = fmaf(acc[mt * 4 + nt][e], WSCALE2_INV, -(gr == gcc ? 1.f : 0.f));
                        lsum = fmaf(d, d, lsum);
                    }
                }
            }
        }
        lsum = warpSum(lsum);
        __shared__ float red[8];
        if (lane == 0) red[wid] = lsum;
        __syncthreads();
        if (tid == 0) {
            float a = 0.f;
            #pragma unroll
            for (int i = 0; i < 8; i++) a += red[i];
            float w = (ti == tj) ? 1.f : 2.f;
            g_otp[t] = (double)(a * w);
        }
    }
}

// ---------------- cov loss reduce (pair-balanced, float4) -----------------
__global__ __launch_bounds__(256) void k_covred() {
    __shared__ double swk[8];
    const float invB = 1.0f / (float)B_ROWS;
    int tid = threadIdx.x;
    double local = 0.0;
    for (int pr = blockIdx.x; pr < CF / 2; pr += NB_CR) {
        #pragma unroll
        for (int h = 0; h < 2; h++) {
            int r = h ? (CF - 1 - pr) : pr;
            float mur = g_musum[r] * invB;
            const float4* row0 = (const float4*)&g_covp[0][(size_t)r * CF];
            const float4* row1 = (const float4*)&g_covp[1][(size_t)r * CF];
            const float4* mus  = (const float4*)g_musum;
            int n4 = (r + 1) >> 2;          // full quads with c+3 <= r
            float facc = 0.f;
            for (int i4 = tid; i4 < n4; i4 += 256) {
                float4 a = row0[i4];
                float4 b = row1[i4];
                float4 m = mus[i4];
                int c0 = i4 * 4;
                float v0 = fmaf(a.x + b.x, invB, -mur * (m.x * invB));
                float v1 = fmaf(a.y + b.y, invB, -mur * (m.y * invB));
                float v2 = fmaf(a.z + b.z, invB, -mur * (m.z * invB));
                float v3 = fmaf(a.w + b.w, invB, -mur * (m.w * invB));
                float d0 = v0 - (c0 + 0 == r ? 1.f : 0.f);
                float d1 = v1 - (c0 + 1 == r ? 1.f : 0.f);
                float d2 = v2 - (c0 + 2 == r ? 1.f : 0.f);
                float d3 = v3 - (c0 + 3 == r ? 1.f : 0.f);
                float w0 = (c0 + 0 < r) ? 2.f : 1.f;
                float w1 = (c0 + 1 < r) ? 2.f : 1.f;
                float w2 = (c0 + 2 < r) ? 2.f : 1.f;
                float w3 = (c0 + 3 < r) ? 2.f : 1.f;
                facc += w0 * d0 * d0 + w1 * d1 * d1 + w2 * d2 * d2 + w3 * d3 * d3;
            }
            // remainder columns [n4*4, r]
            int rem0 = n4 * 4;
            if (tid <= r - rem0) {
                int c = rem0 + tid;
                float v = g_covp[0][(size_t)r * CF + c] + g_covp[1][(size_t)r * CF + c];
                float muc = g_musum[c] * invB;
                float cov = fmaf(v, invB, -mur * muc);
                float d = cov - (r == c ? 1.f : 0.f);
                float wgt = (c < r) ? 2.f : 1.f;
                facc += wgt * d * d;
            }
            local += (double)facc;
        }
    }
    #pragma unroll
    for (int o = 16; o; o >>= 1) local += __shfl_xor_sync(0xffffffffu, local, o);
    if ((tid & 31) == 0) swk[tid >> 5] = local;
    __syncthreads();
    if (tid == 0) {
        double a = 0.0;
        #pragma unroll
        for (int i = 0; i < 8; i++) a += swk[i];
        g_cvp[blockIdx.x] = a;
    }
}

// ---------------- finalize ----------------
__global__ void k_final(float* out) {
    __shared__ double sred[8][6];
    int tid = threadIdx.x, lane = tid & 31, wid = tid >> 5;
    double nll = 0, l1 = 0, l2q = 0, kl = 0, cov = 0, ort = 0;
    for (int i = tid; i < NB_N;  i += 256) nll += (double)g_pn[i];
    for (int i = tid; i < NB_W;  i += 256) { l1 += (double)g_p1[i]; l2q += (double)g_p2[i]; }
    for (int i = tid; i < NB_F;  i += 256) kl  += (double)g_klp2[i];
    for (int i = tid; i < NB_CR; i += 256) cov += g_cvp[i];
    for (int i = tid; i < NT_ORT; i += 256) ort += g_otp[i];
    #pragma unroll
    for (int o = 16; o; o >>= 1) {
        nll += __shfl_xor_sync(0xffffffffu, nll, o);
        l1  += __shfl_xor_sync(0xffffffffu, l1, o);
        l2q += __shfl_xor_sync(0xffffffffu, l2q, o);
        kl  += __shfl_xor_sync(0xffffffffu, kl, o);
        cov += __shfl_xor_sync(0xffffffffu, cov, o);
        ort += __shfl_xor_sync(0xffffffffu, ort, o);
    }
    if (lane == 0) {
        sred[wid][0] = nll; sred[wid][1] = l1; sred[wid][2] = l2q;
        sred[wid][3] = kl;  sred[wid][4] = cov; sred[wid][5] = ort;
    }
    __syncthreads();
    if (tid == 0) {
        double a[6] = {0, 0, 0, 0, 0, 0};
        for (int i = 0; i < 8; i++)
            for (int j = 0; j < 6; j++) a[j] += sred[i][j];
        double loss = -a[0] / (double)B_ROWS
                    + 0.2 * (a[3] / (double)B_ROWS)
                    + 0.2 * a[4]
                    + 0.1 * a[5]
                    + 0.1 * a[1]
                    + 0.1 * sqrt(a[2]);
        out[0] = (float)loss;
    }
}

// ---------------- launch ----------------
extern "C" void kernel_launch(void* const* d_in, const int* in_sizes, int n_in,
                              void* d_out, int out_size) {
    const float* out_lp = nullptr;
    const void*  tgt = nullptr;
    const float* W = nullptr;
    const float* F = nullptr;
    for (int i = 0; i < n_in; i++) {
        long long sz = in_sizes[i];
        if (sz == (long long)B_ROWS * NCLS) out_lp = (const float*)d_in[i];
        else if (sz == B_ROWS)              tgt   = d_in[i];
        else if (sz == (long long)NCLS * CF) W    = (const float*)d_in[i];
        else if (sz == (long long)B_ROWS * CF) F  = (const float*)d_in[i];
    }
    if (!out_lp || !tgt || !W || !F) return;

    static void* musum_addr = nullptr;
    static int smem_set = 0;
    if (!smem_set) {
        cudaFuncSetAttribute(k_mma3, cudaFuncAttributeMaxDynamicSharedMemorySize, SMEM_MMA);
        cudaGetSymbolAddress(&musum_addr, g_musum);
        smem_set = 1;
    }

    cudaMemsetAsync(musum_addr, 0, CF * sizeof(float));     // node 1
    k_pf<<<NB_PF, 256>>>(F, W, out_lp, tgt);                // node 2
    k_mma3<<<SPLITC * NT_COV + NT_ORT, 256, SMEM_MMA>>>();  // node 3
    k_covred<<<NB_CR, 256>>>();                             // node 4
    k_final<<<1, 256>>>((float*)d_out);                     // node 5
}